// round 2
// baseline (speedup 1.0000x reference)
#include <cuda_runtime.h>

#define NN 100000
#define SUBJ_F 1000
#define DEMO_F 10
#define H1 512
#define H2 256
#define HG 128

// ---------------- scratch (static device globals; no allocation) ----------------
__device__ float g_h[(size_t)NN * H1];      // 204.8 MB
__device__ float g_subj[(size_t)NN * H2];   // 102.4 MB
__device__ float g_xt[(size_t)NN * HG];     //  51.2 MB
__device__ float g_agg[(size_t)NN * HG];    //  51.2 MB
__device__ float g_deg[NN];
__device__ float g_dinv[NN];
__device__ float g_scratch;

// ---------------- SGEMM: C[M,N] = op(A[M,K] @ B[K,N] (+C) (+bias) (relu)) -------
// BM=128, BN=128, BK=8, 256 threads, 8x8 per thread.
#define BM 128
#define BN 128
#define BK 8

__global__ __launch_bounds__(256, 2)
void sgemm_kernel(const float* __restrict__ A, int lda,
                  const float* __restrict__ B, int ldb,
                  float* __restrict__ C, int ldc,
                  int M, int N, int K,
                  const float* __restrict__ bias,
                  int do_relu, int accum)
{
    __shared__ float As[BK][BM];
    __shared__ float Bs[BK][BN];

    const int bm = blockIdx.y * BM;
    const int bn = blockIdx.x * BN;
    const int tid = threadIdx.x;

    // A-load mapping: thread -> (row = tid>>1, 4 consecutive k at (tid&1)*4)
    const int arow = tid >> 1;
    const int ak   = (tid & 1) * 4;
    // B-load mapping: thread -> (k-row = tid>>5, 4 consecutive cols at (tid&31)*4)
    const int brow = tid >> 5;
    const int bcol = (tid & 31) * 4;

    const int ty = tid >> 4;   // 0..15 -> row group of 8
    const int tx = tid & 15;   // 0..15 -> col group of 8

    float acc[8][8];
#pragma unroll
    for (int i = 0; i < 8; i++)
#pragma unroll
        for (int j = 0; j < 8; j++) acc[i][j] = 0.f;

    const int grow = bm + arow;

    for (int kt = 0; kt < K; kt += BK) {
        // load A tile (scalar: lda may be odd, e.g. 1010)
        float av[4];
#pragma unroll
        for (int i = 0; i < 4; i++) {
            int gk = kt + ak + i;
            av[i] = (grow < M && gk < K) ? A[(size_t)grow * lda + gk] : 0.f;
        }
#pragma unroll
        for (int i = 0; i < 4; i++) As[ak + i][arow] = av[i];

        // load B tile (vector: ldb % 4 == 0 and base 16B-aligned for our calls)
        float4 bv = make_float4(0.f, 0.f, 0.f, 0.f);
        int gk = kt + brow;
        if (gk < K) bv = *reinterpret_cast<const float4*>(&B[(size_t)gk * ldb + bn + bcol]);
        *reinterpret_cast<float4*>(&Bs[brow][bcol]) = bv;

        __syncthreads();

#pragma unroll
        for (int kk = 0; kk < BK; kk++) {
            float a[8], b[8];
#pragma unroll
            for (int i = 0; i < 8; i++) a[i] = As[kk][ty * 8 + i];
#pragma unroll
            for (int j = 0; j < 8; j++) b[j] = Bs[kk][tx * 8 + j];
#pragma unroll
            for (int i = 0; i < 8; i++)
#pragma unroll
                for (int j = 0; j < 8; j++) acc[i][j] = fmaf(a[i], b[j], acc[i][j]);
        }
        __syncthreads();
    }

#pragma unroll
    for (int i = 0; i < 8; i++) {
        int row = bm + ty * 8 + i;
        if (row >= M) continue;
#pragma unroll
        for (int j = 0; j < 8; j++) {
            int col = bn + tx * 8 + j;
            float v = acc[i][j];
            if (accum) v += C[(size_t)row * ldc + col];
            if (bias)  v += bias[col];
            if (do_relu) v = fmaxf(v, 0.f);
            C[(size_t)row * ldc + col] = v;
        }
    }
}

// ---------------- graph kernels -------------------------------------------------
// edge_index is int32 on device (JAX default x64-disabled downcasts int64->int32).
__global__ void k_init_deg(float* __restrict__ deg, int n)
{
    int i = blockIdx.x * blockDim.x + threadIdx.x;
    if (i < n) deg[i] = 1.0f;          // self-loop contributes 1 to every node
    if (i == 0) g_scratch = 0.f;
}

__global__ void k_deg(const int* __restrict__ ei, int E, float* __restrict__ deg)
{
    int i = blockIdx.x * blockDim.x + threadIdx.x;
    if (i < E) atomicAdd(&deg[ei[E + i]], 1.0f);
}

__global__ void k_dinv(const float* __restrict__ deg, float* __restrict__ dinv, int n)
{
    int i = blockIdx.x * blockDim.x + threadIdx.x;
    if (i < n) dinv[i] = rsqrtf(deg[i]);   // deg >= 1 always (self loop)
}

// agg init = self-loop term, non-atomic: agg[n,:] = xt[n,:] * dinv[n]^2
__global__ void k_agg_init(const float* __restrict__ xt, const float* __restrict__ dinv,
                           float* __restrict__ agg, int total)
{
    int i = blockIdx.x * blockDim.x + threadIdx.x;
    if (i < total) {
        int n = i >> 7;
        float d = dinv[n];
        agg[i] = xt[i] * d * d;
    }
}

// one warp per edge: agg[dst,:] += xt[src,:] * dinv[src]*dinv[dst]
__global__ void k_edge(const int* __restrict__ ei, int E,
                       const float* __restrict__ xt, const float* __restrict__ dinv,
                       float* __restrict__ agg)
{
    int warp = (blockIdx.x * blockDim.x + threadIdx.x) >> 5;
    int lane = threadIdx.x & 31;
    if (warp >= E) return;
    int s = ei[warp];
    int d = ei[E + warp];
    float norm = dinv[s] * dinv[d];
    const float4* xs = reinterpret_cast<const float4*>(xt + (size_t)s * HG);
    float* ad = agg + (size_t)d * HG;
    float4 v = xs[lane];                    // 32 lanes x float4 = 128 floats
    atomicAdd(&ad[lane * 4 + 0], v.x * norm);
    atomicAdd(&ad[lane * 4 + 1], v.y * norm);
    atomicAdd(&ad[lane * 4 + 2], v.z * norm);
    atomicAdd(&ad[lane * 4 + 3], v.w * norm);
}

// sum over (n,c) of relu(agg + bg[c]) * Wo[c]  -> g_scratch
__global__ void k_reduce(const float* __restrict__ agg, const float* __restrict__ bg,
                         const float* __restrict__ Wo, int total)
{
    float local = 0.f;
    for (int i = blockIdx.x * blockDim.x + threadIdx.x; i < total; i += gridDim.x * blockDim.x) {
        int c = i & (HG - 1);
        float v = agg[i] + bg[c];
        if (v > 0.f) local += v * Wo[c];
    }
    // block reduction
#pragma unroll
    for (int off = 16; off > 0; off >>= 1)
        local += __shfl_down_sync(0xffffffffu, local, off);
    __shared__ float red[8];
    int lane = threadIdx.x & 31, wid = threadIdx.x >> 5;
    if (lane == 0) red[wid] = local;
    __syncthreads();
    if (wid == 0) {
        float v = (lane < (blockDim.x >> 5)) ? red[lane] : 0.f;
#pragma unroll
        for (int off = 4; off > 0; off >>= 1)
            v += __shfl_down_sync(0xffffffffu, v, off);
        if (lane == 0) atomicAdd(&g_scratch, v);
    }
}

__global__ void k_finalize(float* __restrict__ out, const float* __restrict__ bo, int n)
{
    out[0] = g_scratch / (float)n + bo[0];
}

// ---------------- launch --------------------------------------------------------
extern "C" void kernel_launch(void* const* d_in, const int* in_sizes, int n_in,
                              void* d_out, int out_size)
{
    const float* x  = (const float*)d_in[0];
    const int*   ei = (const int*)d_in[1];
    const float* W1 = (const float*)d_in[2];
    const float* b1 = (const float*)d_in[3];
    const float* W2 = (const float*)d_in[4];
    const float* b2 = (const float*)d_in[5];
    const float* Wg = (const float*)d_in[6];
    const float* bg = (const float*)d_in[7];
    const float* Wo = (const float*)d_in[8];
    const float* bo = (const float*)d_in[9];

    const int N = in_sizes[0] / (SUBJ_F + DEMO_F);
    const int E = in_sizes[1] / 2;

    float *h, *subj, *xt, *agg, *deg, *dinv;
    cudaGetSymbolAddress((void**)&h,    g_h);
    cudaGetSymbolAddress((void**)&subj, g_subj);
    cudaGetSymbolAddress((void**)&xt,   g_xt);
    cudaGetSymbolAddress((void**)&agg,  g_agg);
    cudaGetSymbolAddress((void**)&deg,  g_deg);
    cudaGetSymbolAddress((void**)&dinv, g_dinv);

    // degree / normalization (independent of GEMM chain)
    k_init_deg<<<(N + 255) / 256, 256>>>(deg, N);
    k_deg<<<(E + 255) / 256, 256>>>(ei, E, deg);
    k_dinv<<<(N + 255) / 256, 256>>>(deg, dinv, N);

    const int mgrid = (N + BM - 1) / BM;   // 782
    // h = relu(x[:, :1000] @ W1 + b1)
    sgemm_kernel<<<dim3(H1 / BN, mgrid), 256>>>(x, SUBJ_F + DEMO_F, W1, H1, h, H1,
                                                N, H1, SUBJ_F, b1, 1, 0);
    // subj = h @ W2 + b2
    sgemm_kernel<<<dim3(H2 / BN, mgrid), 256>>>(h, H1, W2, H2, subj, H2,
                                                N, H2, H1, b2, 0, 0);
    // xt = subj @ Wg[:256]
    sgemm_kernel<<<dim3(HG / BN, mgrid), 256>>>(subj, H2, Wg, HG, xt, HG,
                                                N, HG, H2, nullptr, 0, 0);
    // xt += demo @ Wg[256:266]
    sgemm_kernel<<<dim3(HG / BN, mgrid), 256>>>(x + SUBJ_F, SUBJ_F + DEMO_F,
                                                Wg + (size_t)H2 * HG, HG, xt, HG,
                                                N, HG, DEMO_F, nullptr, 0, 1);

    // agg = self-loop term, then scatter edges, then pooled dot
    k_agg_init<<<(N * HG + 255) / 256, 256>>>(xt, dinv, agg, N * HG);
    k_edge<<<((size_t)E * 32 + 255) / 256, 256>>>(ei, E, xt, dinv, agg);
    k_reduce<<<4096, 256>>>(agg, bg, Wo, N * HG);
    k_finalize<<<1, 1>>>((float*)d_out, bo, N);
}

// round 4
// speedup vs baseline: 1.9066x; 1.9066x over previous
#include <cuda_runtime.h>
#include <cstdint>

#define NN 100000
#define SUBJ_F 1000
#define DEMO_F 10
#define H1 512
#define H2 256
#define HG 128

// ---------------- scratch (static device globals; no allocation) ----------------
__device__ float g_h[(size_t)NN * H1];      // 204.8 MB
__device__ float g_subj[(size_t)NN * H2];   // 102.4 MB
__device__ float g_xt[(size_t)NN * HG];     //  51.2 MB
__device__ float g_agg[(size_t)NN * HG];    //  51.2 MB
__device__ float g_deg[NN];
__device__ float g_dinv[NN];
__device__ float g_scratch;

// ---------------- helpers -------------------------------------------------------
__device__ __forceinline__ uint32_t f32_to_tf32_rna(float x) {
    uint32_t o;
    asm("cvt.rna.tf32.f32 %0, %1;" : "=r"(o) : "f"(x));
    return o;
}

// ---------------- tf32 tensor-core GEMM -----------------------------------------
// C[M,N] = A[M,K] @ B[K,N] (+bias)(relu). Row-major A (lda), row-major B (ldb=N).
// CTA tile 128x128x32, 256 threads = 8 warps (2x4), warp tile 64x32, mma m16n8k8.
#define TBM 128
#define TBN 128
#define TBK 32
#define SPAD 4

__global__ __launch_bounds__(256, 2)
void tgemm_kernel(const float* __restrict__ A, int lda,
                  const float* __restrict__ B, int ldb,
                  float* __restrict__ C, int ldc,
                  int M, int N, int K,
                  const float* __restrict__ bias, int do_relu)
{
    __shared__ uint32_t As[TBK][TBM + SPAD];
    __shared__ uint32_t Bs[TBK][TBN + SPAD];

    const int tid  = threadIdx.x;
    const int lane = tid & 31;
    const int wid  = tid >> 5;
    const int bm = blockIdx.y * TBM;
    const int bn = blockIdx.x * TBN;

    const int warpM = (wid >> 2) * 64;   // 0 or 64
    const int warpN = (wid & 3) * 32;    // 0,32,64,96
    const int grp = lane >> 2;           // 0..7
    const int tig = lane & 3;            // 0..3

    // A tile load map: 2 threads per row, 16 k each (8 x float2)
    const int arow = tid >> 1;
    const int akb  = (tid & 1) * 16;
    // B tile load map: 8 threads per k-row, 16 n each (4 x float4)
    const int bkr = tid >> 3;
    const int bnb = (tid & 7) * 16;

    float acc[4][4][4];
#pragma unroll
    for (int i = 0; i < 4; i++)
#pragma unroll
        for (int j = 0; j < 4; j++)
#pragma unroll
            for (int r = 0; r < 4; r++) acc[i][j][r] = 0.f;

    const int grow = bm + arow;
    const bool arow_ok = (grow < M);
    const float* Arow = A + (size_t)grow * lda;

    for (int kt = 0; kt < K; kt += TBK) {
        // ---- A tile: global -> smem (tf32-rounded) ----
#pragma unroll
        for (int j = 0; j < 8; j++) {
            int gk = kt + akb + 2 * j;
            float2 v = make_float2(0.f, 0.f);
            if (arow_ok && gk < K)
                v = *reinterpret_cast<const float2*>(Arow + gk);
            As[akb + 2 * j    ][arow] = f32_to_tf32_rna(v.x);
            As[akb + 2 * j + 1][arow] = f32_to_tf32_rna(v.y);
        }
        // ---- B tile: 4 x float4 per thread = full 16-column span ----
        {
            int gk = kt + bkr;
#pragma unroll
            for (int j = 0; j < 4; j++) {
                float4 v = make_float4(0.f, 0.f, 0.f, 0.f);
                if (gk < K)
                    v = *reinterpret_cast<const float4*>(B + (size_t)gk * ldb + bn + bnb + 4 * j);
                Bs[bkr][bnb + 4 * j + 0] = f32_to_tf32_rna(v.x);
                Bs[bkr][bnb + 4 * j + 1] = f32_to_tf32_rna(v.y);
                Bs[bkr][bnb + 4 * j + 2] = f32_to_tf32_rna(v.z);
                Bs[bkr][bnb + 4 * j + 3] = f32_to_tf32_rna(v.w);
            }
        }
        __syncthreads();

#pragma unroll
        for (int kk = 0; kk < TBK; kk += 8) {
            uint32_t af[4][4], bf[4][2];
#pragma unroll
            for (int i = 0; i < 4; i++) {
                int r0 = warpM + i * 16 + grp;
                af[i][0] = As[kk + tig    ][r0];
                af[i][1] = As[kk + tig    ][r0 + 8];
                af[i][2] = As[kk + tig + 4][r0];
                af[i][3] = As[kk + tig + 4][r0 + 8];
            }
#pragma unroll
            for (int n = 0; n < 4; n++) {
                int c0 = warpN + n * 8 + grp;
                bf[n][0] = Bs[kk + tig    ][c0];
                bf[n][1] = Bs[kk + tig + 4][c0];
            }
#pragma unroll
            for (int i = 0; i < 4; i++)
#pragma unroll
                for (int n = 0; n < 4; n++) {
                    asm volatile(
                        "mma.sync.aligned.m16n8k8.row.col.f32.tf32.tf32.f32 "
                        "{%0,%1,%2,%3}, {%4,%5,%6,%7}, {%8,%9}, {%0,%1,%2,%3};\n"
                        : "+f"(acc[i][n][0]), "+f"(acc[i][n][1]),
                          "+f"(acc[i][n][2]), "+f"(acc[i][n][3])
                        : "r"(af[i][0]), "r"(af[i][1]), "r"(af[i][2]), "r"(af[i][3]),
                          "r"(bf[n][0]), "r"(bf[n][1]));
                }
        }
        __syncthreads();
    }

    // ---- epilogue ----
#pragma unroll
    for (int i = 0; i < 4; i++) {
#pragma unroll
        for (int n = 0; n < 4; n++) {
            int col = bn + warpN + n * 8 + tig * 2;
            float bx = 0.f, by = 0.f;
            if (bias) { bx = bias[col]; by = bias[col + 1]; }
            int row0 = bm + warpM + i * 16 + grp;
            int row1 = row0 + 8;
            if (row0 < M) {
                float vx = acc[i][n][0] + bx, vy = acc[i][n][1] + by;
                if (do_relu) { vx = fmaxf(vx, 0.f); vy = fmaxf(vy, 0.f); }
                *reinterpret_cast<float2*>(C + (size_t)row0 * ldc + col) = make_float2(vx, vy);
            }
            if (row1 < M) {
                float vx = acc[i][n][2] + bx, vy = acc[i][n][3] + by;
                if (do_relu) { vx = fmaxf(vx, 0.f); vy = fmaxf(vy, 0.f); }
                *reinterpret_cast<float2*>(C + (size_t)row1 * ldc + col) = make_float2(vx, vy);
            }
        }
    }
}

// ---------------- small FFMA GEMM (K=10 demo part, accumulates into C) ----------
#define BM 128
#define BN 128
#define BK 8

__global__ __launch_bounds__(256, 2)
void sgemm_kernel(const float* __restrict__ A, int lda,
                  const float* __restrict__ B, int ldb,
                  float* __restrict__ C, int ldc,
                  int M, int N, int K,
                  const float* __restrict__ bias,
                  int do_relu, int accum)
{
    __shared__ float As[BK][BM];
    __shared__ float Bs[BK][BN];

    const int bm = blockIdx.y * BM;
    const int bn = blockIdx.x * BN;
    const int tid = threadIdx.x;

    const int arow = tid >> 1;
    const int ak   = (tid & 1) * 4;
    const int brow = tid >> 5;
    const int bcol = (tid & 31) * 4;

    const int ty = tid >> 4;
    const int tx = tid & 15;

    float acc[8][8];
#pragma unroll
    for (int i = 0; i < 8; i++)
#pragma unroll
        for (int j = 0; j < 8; j++) acc[i][j] = 0.f;

    const int grow = bm + arow;

    for (int kt = 0; kt < K; kt += BK) {
        float av[4];
#pragma unroll
        for (int i = 0; i < 4; i++) {
            int gk = kt + ak + i;
            av[i] = (grow < M && gk < K) ? A[(size_t)grow * lda + gk] : 0.f;
        }
#pragma unroll
        for (int i = 0; i < 4; i++) As[ak + i][arow] = av[i];

        float4 bv = make_float4(0.f, 0.f, 0.f, 0.f);
        int gk = kt + brow;
        if (gk < K) bv = *reinterpret_cast<const float4*>(&B[(size_t)gk * ldb + bn + bcol]);
        *reinterpret_cast<float4*>(&Bs[brow][bcol]) = bv;

        __syncthreads();

#pragma unroll
        for (int kk = 0; kk < BK; kk++) {
            float a[8], b[8];
#pragma unroll
            for (int i = 0; i < 8; i++) a[i] = As[kk][ty * 8 + i];
#pragma unroll
            for (int j = 0; j < 8; j++) b[j] = Bs[kk][tx * 8 + j];
#pragma unroll
            for (int i = 0; i < 8; i++)
#pragma unroll
                for (int j = 0; j < 8; j++) acc[i][j] = fmaf(a[i], b[j], acc[i][j]);
        }
        __syncthreads();
    }

#pragma unroll
    for (int i = 0; i < 8; i++) {
        int row = bm + ty * 8 + i;
        if (row >= M) continue;
#pragma unroll
        for (int j = 0; j < 8; j++) {
            int col = bn + tx * 8 + j;
            float v = acc[i][j];
            if (accum) v += C[(size_t)row * ldc + col];
            if (bias)  v += bias[col];
            if (do_relu) v = fmaxf(v, 0.f);
            C[(size_t)row * ldc + col] = v;
        }
    }
}

// ---------------- graph kernels -------------------------------------------------
// edge_index is int32 on device (JAX default x64-disabled downcasts int64->int32).
__global__ void k_init_deg(float* __restrict__ deg, int n)
{
    int i = blockIdx.x * blockDim.x + threadIdx.x;
    if (i < n) deg[i] = 1.0f;          // self-loop contributes 1 to every node
    if (i == 0) g_scratch = 0.f;
}

__global__ void k_deg(const int* __restrict__ ei, int E, float* __restrict__ deg)
{
    int i = blockIdx.x * blockDim.x + threadIdx.x;
    if (i < E) atomicAdd(&deg[ei[E + i]], 1.0f);
}

__global__ void k_dinv(const float* __restrict__ deg, float* __restrict__ dinv, int n)
{
    int i = blockIdx.x * blockDim.x + threadIdx.x;
    if (i < n) dinv[i] = rsqrtf(deg[i]);   // deg >= 1 always (self loop)
}

// agg init = self-loop term, non-atomic: agg[n,:] = xt[n,:] * dinv[n]^2
__global__ void k_agg_init(const float* __restrict__ xt, const float* __restrict__ dinv,
                           float* __restrict__ agg, int total)
{
    int i = blockIdx.x * blockDim.x + threadIdx.x;
    if (i < total) {
        int n = i >> 7;
        float d = dinv[n];
        agg[i] = xt[i] * d * d;
    }
}

// one warp per edge: agg[dst,:] += xt[src,:] * dinv[src]*dinv[dst]
__global__ void k_edge(const int* __restrict__ ei, int E,
                       const float* __restrict__ xt, const float* __restrict__ dinv,
                       float* __restrict__ agg)
{
    int warp = (blockIdx.x * blockDim.x + threadIdx.x) >> 5;
    int lane = threadIdx.x & 31;
    if (warp >= E) return;
    int s = ei[warp];
    int d = ei[E + warp];
    float norm = dinv[s] * dinv[d];
    const float4* xs = reinterpret_cast<const float4*>(xt + (size_t)s * HG);
    float* ad = agg + (size_t)d * HG;
    float4 v = xs[lane];                    // 32 lanes x float4 = 128 floats
    atomicAdd(&ad[lane * 4 + 0], v.x * norm);
    atomicAdd(&ad[lane * 4 + 1], v.y * norm);
    atomicAdd(&ad[lane * 4 + 2], v.z * norm);
    atomicAdd(&ad[lane * 4 + 3], v.w * norm);
}

// sum over (n,c) of relu(agg + bg[c]) * Wo[c]  -> g_scratch
__global__ void k_reduce(const float* __restrict__ agg, const float* __restrict__ bg,
                         const float* __restrict__ Wo, int total)
{
    float local = 0.f;
    for (int i = blockIdx.x * blockDim.x + threadIdx.x; i < total; i += gridDim.x * blockDim.x) {
        int c = i & (HG - 1);
        float v = agg[i] + bg[c];
        if (v > 0.f) local += v * Wo[c];
    }
#pragma unroll
    for (int off = 16; off > 0; off >>= 1)
        local += __shfl_down_sync(0xffffffffu, local, off);
    __shared__ float red[8];
    int lane = threadIdx.x & 31, wid = threadIdx.x >> 5;
    if (lane == 0) red[wid] = local;
    __syncthreads();
    if (wid == 0) {
        float v = (lane < (blockDim.x >> 5)) ? red[lane] : 0.f;
#pragma unroll
        for (int off = 4; off > 0; off >>= 1)
            v += __shfl_down_sync(0xffffffffu, v, off);
        if (lane == 0) atomicAdd(&g_scratch, v);
    }
}

__global__ void k_finalize(float* __restrict__ out, const float* __restrict__ bo, int n)
{
    out[0] = g_scratch / (float)n + bo[0];
}

// ---------------- launch --------------------------------------------------------
extern "C" void kernel_launch(void* const* d_in, const int* in_sizes, int n_in,
                              void* d_out, int out_size)
{
    const float* x  = (const float*)d_in[0];
    const int*   ei = (const int*)d_in[1];
    const float* W1 = (const float*)d_in[2];
    const float* b1 = (const float*)d_in[3];
    const float* W2 = (const float*)d_in[4];
    const float* b2 = (const float*)d_in[5];
    const float* Wg = (const float*)d_in[6];
    const float* bg = (const float*)d_in[7];
    const float* Wo = (const float*)d_in[8];
    const float* bo = (const float*)d_in[9];

    const int N = in_sizes[0] / (SUBJ_F + DEMO_F);
    const int E = in_sizes[1] / 2;

    float *h, *subj, *xt, *agg, *deg, *dinv;
    cudaGetSymbolAddress((void**)&h,    g_h);
    cudaGetSymbolAddress((void**)&subj, g_subj);
    cudaGetSymbolAddress((void**)&xt,   g_xt);
    cudaGetSymbolAddress((void**)&agg,  g_agg);
    cudaGetSymbolAddress((void**)&deg,  g_deg);
    cudaGetSymbolAddress((void**)&dinv, g_dinv);

    // degree / normalization (independent of GEMM chain)
    k_init_deg<<<(N + 255) / 256, 256>>>(deg, N);
    k_deg<<<(E + 255) / 256, 256>>>(ei, E, deg);
    k_dinv<<<(N + 255) / 256, 256>>>(deg, dinv, N);

    const int mgrid = (N + TBM - 1) / TBM;   // 782
    // h = relu(x[:, :1000] @ W1 + b1)            [tensor, tf32]
    tgemm_kernel<<<dim3(H1 / TBN, mgrid), 256>>>(x, SUBJ_F + DEMO_F, W1, H1, h, H1,
                                                 N, H1, SUBJ_F, b1, 1);
    // subj = h @ W2 + b2                         [tensor, tf32]
    tgemm_kernel<<<dim3(H2 / TBN, mgrid), 256>>>(h, H1, W2, H2, subj, H2,
                                                 N, H2, H1, b2, 0);
    // xt = subj @ Wg[:256]                       [tensor, tf32]
    tgemm_kernel<<<dim3(HG / TBN, mgrid), 256>>>(subj, H2, Wg, HG, xt, HG,
                                                 N, HG, H2, nullptr, 0);
    // xt += demo @ Wg[256:266]                   [FFMA, tiny K]
    sgemm_kernel<<<dim3(HG / BN, (N + BM - 1) / BM), 256>>>(
        x + SUBJ_F, SUBJ_F + DEMO_F, Wg + (size_t)H2 * HG, HG, xt, HG,
        N, HG, DEMO_F, nullptr, 0, 1);

    // agg = self-loop term, then scatter edges, then pooled dot
    k_agg_init<<<(N * HG + 255) / 256, 256>>>(xt, dinv, agg, N * HG);
    k_edge<<<((size_t)E * 32 + 255) / 256, 256>>>(ei, E, xt, dinv, agg);
    k_reduce<<<4096, 256>>>(agg, bg, Wo, N * HG);
    k_finalize<<<1, 1>>>((float*)d_out, bo, N);
}